// round 12
// baseline (speedup 1.0000x reference)
#include <cuda_runtime.h>
#include <cuda_fp16.h>
#include <cstdint>

#define T_DIM 4
#define M_DIM 16384
#define R_DIM 65536
#define D_DIM 512
#define MD ((size_t)M_DIM * D_DIM)
#define RD ((size_t)R_DIM * D_DIM)

// scratch (device globals; no allocs allowed)
__device__ __align__(16) __half  g_X0[RD];                 // fp16(x)
__device__ __align__(16) __half  g_Yq[RD];                 // projection outputs (fp16)
__device__ __align__(16) __half  g_Yk[RD];
__device__ __align__(16) __half  g_Yv[RD];
__device__ __align__(16) __half  g_S[RD];                  // spike-attention state (exact ints)
__device__ __align__(16) __half  g_Wh[4 * D_DIM * D_DIM];  // fp16 planes of Wq,Wk,Wv,Wp
__device__ __align__(4)  uint8_t g_flag[MD];               // per-(m,d) near-threshold mask

// ---------------- helpers ----------------
__device__ __forceinline__ uint32_t smem_u32(const void* p) {
    uint32_t a;
    asm("{ .reg .u64 t; cvta.to.shared.u64 t, %1; cvt.u32.u64 %0, t; }" : "=r"(a) : "l"(p));
    return a;
}
#define SW128(o) ((o) ^ (((o) >> 3) & 0x70))
#define CP_ASYNC16(sa, g) \
    asm volatile("cp.async.cg.shared.global [%0], [%1], 16;" :: "r"((uint32_t)(sa)), "l"(g))
#define CP_COMMIT() asm volatile("cp.async.commit_group;" ::: "memory")
#define CP_WAIT1()  asm volatile("cp.async.wait_group 1;" ::: "memory")
#define CP_WAIT0()  asm volatile("cp.async.wait_group 0;" ::: "memory")
#define LDMX4(r0, r1, r2, r3, a)                                            \
    asm volatile("ldmatrix.sync.aligned.m8n8.x4.shared.b16 {%0,%1,%2,%3}, [%4];" \
                 : "=r"(r0), "=r"(r1), "=r"(r2), "=r"(r3) : "r"(a))
#define MMA16816(c, a, b0, b1)                                              \
    asm volatile("mma.sync.aligned.m16n8k16.row.col.f32.f16.f16.f32 "       \
                 "{%0,%1,%2,%3},{%4,%5,%6,%7},{%8,%9},{%0,%1,%2,%3};"       \
                 : "+f"((c)[0]), "+f"((c)[1]), "+f"((c)[2]), "+f"((c)[3])   \
                 : "r"((a)[0]), "r"((a)[1]), "r"((a)[2]), "r"((a)[3]),      \
                   "r"(b0), "r"(b1))

// ---------------- fp32 -> fp16 pre-conversions ----------------
__global__ __launch_bounds__(256) void split_x(const float* __restrict__ x) {
    const size_t i = ((size_t)blockIdx.x * 256 + threadIdx.x) * 4;
    const float4 v = *(const float4*)(x + i);
    __half h[4] = {__float2half_rn(v.x), __float2half_rn(v.y),
                   __float2half_rn(v.z), __float2half_rn(v.w)};
    *(uint2*)&g_X0[i] = *(uint2*)h;
}

__global__ __launch_bounds__(256) void prep_w(const float* __restrict__ W0,
                                              const float* __restrict__ W1,
                                              const float* __restrict__ W2,
                                              const float* __restrict__ W3) {
    const int idx = blockIdx.x * 256 + threadIdx.x;   // 0 .. 4*262144-1
    const int mat = idx >> 18, rem = idx & 0x3FFFF;
    const float* W = (mat == 0) ? W0 : (mat == 1) ? W1 : (mat == 2) ? W2 : W3;
    g_Wh[(size_t)mat * 262144 + rem] = __float2half_rn(W[rem]);
}

// ---------------- fused Q/K/V projection GEMM ----------------
// Yq/Yk/Yv[m,n] = sum_k X[m,k] * Wm[n,k]. One A fragment feeds all 3 weight
// matrices: per k16 step 8 LDSM.x4 vs 24 MMA (was 6:16) -> smem crossbar no
// longer binds; A global traffic /3. CTA 128m x 64n, 8 warps of 32x32 per
// matrix, BK=64, SW128 rows, 2-stage cp.async (per-tile compute ~3000cyc >>
// load latency). k-order per output element identical to gemm1p -> bit-exact Y.
__global__ __launch_bounds__(256, 1) void qkv_gemm() {
    extern __shared__ __align__(128) char sm_raw[];
    const uint32_t sb = (smem_u32(sm_raw) + 127) & ~127u;

    const int tid = threadIdx.x, l = tid & 31, wid = tid >> 5;
    const int bm = blockIdx.y * 128, bn = blockIdx.x * 64;
    const int wm = (wid & 3) * 32, wn = (wid >> 2) * 32;

    float acc[3][2][4][4];
#pragma unroll
    for (int mt = 0; mt < 3; mt++)
#pragma unroll
        for (int f = 0; f < 2; f++)
#pragma unroll
            for (int n8 = 0; n8 < 4; n8++)
#pragma unroll
                for (int i = 0; i < 4; i++) acc[mt][f][n8][i] = 0.f;

    // stage layout: A 16KB, then B0/B1/B2 8KB each (40KB/stage, 2 stages)
    auto load_stage = [&](int kt, int st) {
        const int k0 = kt * 64;
        const uint32_t smA = sb + st * 40960, smB = smA + 16384;
        // A: 128 rows x 8 chunks of 16B
#pragma unroll
        for (int j = 0; j < 4; j++) {
            const int row = j * 32 + (tid >> 3), ch = tid & 7;
            CP_ASYNC16(smA + SW128((uint32_t)(row * 128 + ch * 16)),
                       g_X0 + (size_t)(bm + row) * D_DIM + k0 + ch * 8);
        }
        // B: 3 mats x 64 rows x 8 chunks
#pragma unroll
        for (int mt = 0; mt < 3; mt++)
#pragma unroll
            for (int j = 0; j < 2; j++) {
                const int uid = j * 256 + tid;
                const int row = uid >> 3, ch = uid & 7;
                CP_ASYNC16(smB + mt * 8192 + SW128((uint32_t)(row * 128 + ch * 16)),
                           g_Wh + (size_t)mt * 262144 + (size_t)(bn + row) * D_DIM + k0 + ch * 8);
            }
        CP_COMMIT();
    };

    load_stage(0, 0);
    for (int kt = 0; kt < 8; kt++) {
        CP_WAIT0();          // tile kt landed
        __syncthreads();     // warps done with the buffer being refilled below
        if (kt + 1 < 8) load_stage(kt + 1, (kt + 1) & 1);
        const uint32_t smA = sb + (kt & 1) * 40960, smB = smA + 16384;
#pragma unroll
        for (int s = 0; s < 4; s++) {
            uint32_t afr[2][4];
#pragma unroll
            for (int f = 0; f < 2; f++) {   // A: m32 x k16
                const int row = wm + f * 16 + (l & 15);
                const int ch = 2 * s + (l >> 4);
                LDMX4(afr[f][0], afr[f][1], afr[f][2], afr[f][3],
                      smA + SW128((uint32_t)(row * 128 + ch * 16)));
            }
#pragma unroll
            for (int mt = 0; mt < 3; mt++) {  // reuse A frags across all 3 mats
                uint32_t bfr[2][4];
#pragma unroll
                for (int h = 0; h < 2; h++) {
                    const int row = wn + h * 16 + (l & 7) + ((l >> 4) << 3);
                    const int ch = 2 * s + ((l >> 3) & 1);
                    LDMX4(bfr[h][0], bfr[h][1], bfr[h][2], bfr[h][3],
                          smB + mt * 8192 + SW128((uint32_t)(row * 128 + ch * 16)));
                }
#pragma unroll
                for (int f = 0; f < 2; f++)
#pragma unroll
                    for (int n8 = 0; n8 < 4; n8++)
                        MMA16816(acc[mt][f][n8], afr[f],
                                 bfr[n8 >> 1][(n8 & 1) * 2], bfr[n8 >> 1][(n8 & 1) * 2 + 1]);
            }
        }
    }

    const int er = l >> 2, ec = (l & 3) * 2;
#pragma unroll
    for (int mt = 0; mt < 3; mt++) {
        __half* C = (mt == 0) ? g_Yq : (mt == 1) ? g_Yk : g_Yv;
#pragma unroll
        for (int f = 0; f < 2; f++) {
            const int m = bm + wm + f * 16 + er;
#pragma unroll
            for (int n8 = 0; n8 < 4; n8++) {
                const int n = bn + wn + n8 * 8 + ec;
                *(__half2*)&C[(size_t)m * D_DIM + n] =
                    __floats2half2_rn(acc[mt][f][n8][0], acc[mt][f][n8][1]);
                *(__half2*)&C[(size_t)(m + 8) * D_DIM + n] =
                    __floats2half2_rn(acc[mt][f][n8][2], acc[mt][f][n8][3]);
            }
        }
    }
}

// ---------------- single-matrix HMMA GEMM (R11-validated) for the output ----------
__global__ __launch_bounds__(256, 2) void out_gemm(float* __restrict__ C,
                                                   const float* __restrict__ bias) {
    extern __shared__ __align__(128) char sm_raw[];
    const uint32_t sb = (smem_u32(sm_raw) + 127) & ~127u;
    const __half* A = g_S;
    const __half* B = g_Wh + (size_t)3 * 262144;
    const int bm = blockIdx.y * 128, bn = blockIdx.x * 128;
    const int tid = threadIdx.x, l = tid & 31, wid = tid >> 5;
    const int wm = (wid >> 2) * 64, wn = (wid & 3) * 32;

    float acc[4][4][4];
#pragma unroll
    for (int f = 0; f < 4; f++)
#pragma unroll
        for (int n8 = 0; n8 < 4; n8++)
#pragma unroll
            for (int i = 0; i < 4; i++) acc[f][n8][i] = 0.f;

    auto load_stage = [&](int kt, int st) {
        const int k0 = kt * 64;
        const uint32_t smA = sb + st * 32768, smB = smA + 16384;
#pragma unroll
        for (int j = 0; j < 4; j++) {
            const int row = j * 32 + (tid >> 3), ch = tid & 7;
            const uint32_t dst = SW128((uint32_t)(row * 128 + ch * 16));
            CP_ASYNC16(smA + dst, A + (size_t)(bm + row) * D_DIM + k0 + ch * 8);
            CP_ASYNC16(smB + dst, B + (size_t)(bn + row) * D_DIM + k0 + ch * 8);
        }
        CP_COMMIT();
    };

    load_stage(0, 0);
    load_stage(1, 1);
    for (int kt = 0; kt < 8; kt++) {
        if (kt < 7) CP_WAIT1(); else CP_WAIT0();
        __syncthreads();
        if (kt + 2 < 8) load_stage(kt + 2, (kt + 2) % 3);
        const uint32_t smA = sb + (kt % 3) * 32768, smB = smA + 16384;
#pragma unroll
        for (int s = 0; s < 4; s++) {
            uint32_t afr[4][4];
#pragma unroll
            for (int f = 0; f < 4; f++) {
                const int row = wm + f * 16 + (l & 15);
                const int ch = 2 * s + (l >> 4);
                LDMX4(afr[f][0], afr[f][1], afr[f][2], afr[f][3],
                      smA + SW128((uint32_t)(row * 128 + ch * 16)));
            }
            uint32_t bfr[2][4];
#pragma unroll
            for (int h = 0; h < 2; h++) {
                const int row = wn + h * 16 + (l & 7) + ((l >> 4) << 3);
                const int ch = 2 * s + ((l >> 3) & 1);
                LDMX4(bfr[h][0], bfr[h][1], bfr[h][2], bfr[h][3],
                      smB + SW128((uint32_t)(row * 128 + ch * 16)));
            }
#pragma unroll
            for (int f = 0; f < 4; f++)
#pragma unroll
                for (int n8 = 0; n8 < 4; n8++)
                    MMA16816(acc[f][n8], afr[f],
                             bfr[n8 >> 1][(n8 & 1) * 2], bfr[n8 >> 1][(n8 & 1) * 2 + 1]);
        }
    }

    const int er = l >> 2, ec = (l & 3) * 2;
#pragma unroll
    for (int f = 0; f < 4; f++) {
        const int m = bm + wm + f * 16 + er;
#pragma unroll
        for (int n8 = 0; n8 < 4; n8++) {
            const int n = bn + wn + n8 * 8 + ec;
            const float b0v = bias[n], b1v = bias[n + 1];
            *(float2*)&C[(size_t)m * D_DIM + n] =
                make_float2(acc[f][n8][0] + b0v, acc[f][n8][1] + b1v);
            *(float2*)&C[(size_t)(m + 8) * D_DIM + n] =
                make_float2(acc[f][n8][2] + b0v, acc[f][n8][3] + b1v);
        }
    }
}

// ---------------- LIF provisional pass (EPS=5e-3 validated zero-flip margin) ------------
#define LIF_EPS 5e-3f

__global__ __launch_bounds__(256) void lif_attn() {
    const size_t base = ((size_t)blockIdx.x * 256 + threadIdx.x) * 4;

    __half q[T_DIM][4], k[T_DIM][4], v[T_DIM][4], s[T_DIM][4];
#pragma unroll
    for (int t = 0; t < T_DIM; t++) {
        *(uint2*)q[t] = *(const uint2*)&g_Yq[(size_t)t * MD + base];
        *(uint2*)k[t] = *(const uint2*)&g_Yk[(size_t)t * MD + base];
        *(uint2*)v[t] = *(const uint2*)&g_Yv[(size_t)t * MD + base];
    }
    uint32_t flags = 0;
#pragma unroll
    for (int c = 0; c < 4; c++) {
        float sq[T_DIM], sk[T_DIM], sv[T_DIM];
        uint32_t mk = 0;
        float mq = 0.f, mkm = 0.f, mv = 0.f;
#pragma unroll
        for (int t = 0; t < T_DIM; t++) {
            mq = fmaf(0.9f, mq, __half2float(q[t][c]));
            if (fabsf(mq - 1.0f) < LIF_EPS) mk |= 1u;
            sq[t] = (mq >= 1.0f) ? 1.0f : 0.0f; mq -= sq[t];
            mkm = fmaf(0.9f, mkm, __half2float(k[t][c]));
            if (fabsf(mkm - 1.0f) < LIF_EPS) mk |= 2u;
            sk[t] = (mkm >= 1.0f) ? 1.0f : 0.0f; mkm -= sk[t];
            mv = fmaf(0.9f, mv, __half2float(v[t][c]));
            if (fabsf(mv - 1.0f) < LIF_EPS) mk |= 4u;
            sv[t] = (mv >= 1.0f) ? 1.0f : 0.0f; mv -= sv[t];
        }
        flags |= mk << (8 * c);
        float ctx = 0.f;
#pragma unroll
        for (int t = 0; t < T_DIM; t++) {
            ctx += sk[t] * sv[t];
            s[t][c] = __float2half_rn(sq[t] * ctx);   // exact: small integers
        }
    }
    *(uint32_t*)&g_flag[base] = flags;   // mostly 0
#pragma unroll
    for (int t = 0; t < T_DIM; t++)
        *(uint2*)&g_S[(size_t)t * MD + base] = *(uint2*)s[t];
}

// ---------------- exact repair: one CTA per m, x rows staged in smem ------------
__device__ __forceinline__ void exact_spikes_warp(const float* __restrict__ xs,
                                                  const float* __restrict__ W,
                                                  int d, int l, float* sp) {
    const float* w = W + (size_t)d * D_DIM;
    float wv[16];
#pragma unroll
    for (int j = 0; j < 16; j++) wv[j] = w[l * 16 + j];
    float mem = 0.f;
    for (int t = 0; t < T_DIM; t++) {
        const float* xr = xs + t * D_DIM;
        float p = 0.f;
#pragma unroll
        for (int j = 0; j < 16; j++) p = fmaf(xr[l * 16 + j], wv[j], p);
#pragma unroll
        for (int off = 16; off > 0; off >>= 1) p += __shfl_xor_sync(0xffffffffu, p, off);
        mem = fmaf(0.9f, mem, p);
        sp[t] = (mem >= 1.0f) ? 1.0f : 0.0f;
        mem -= sp[t];
    }
}

__device__ __forceinline__ void prov_spikes(const __half* __restrict__ Y,
                                            int m, int d, float* sp) {
    float mem = 0.f;
    for (int t = 0; t < T_DIM; t++) {
        mem = fmaf(0.9f, mem, __half2float(Y[(size_t)t * MD + (size_t)m * D_DIM + d]));
        sp[t] = (mem >= 1.0f) ? 1.0f : 0.0f;
        mem -= sp[t];
    }
}

__global__ __launch_bounds__(128) void repair(const float* __restrict__ x,
                                              const float* __restrict__ Wq,
                                              const float* __restrict__ Wk,
                                              const float* __restrict__ Wv) {
    const int m = blockIdx.x;
    __shared__ float xs[T_DIM * D_DIM];   // 8KB: the 4 x rows of this m
    __shared__ uint16_t list[512];
    __shared__ int cnt;
    const int tid = threadIdx.x;
    if (tid == 0) cnt = 0;
    __syncthreads();
    for (int d = tid; d < D_DIM; d += 128) {
        const uint32_t mk = g_flag[(size_t)m * D_DIM + d];
        if (mk) { int p = atomicAdd(&cnt, 1); list[p] = (uint16_t)(d | (mk << 9)); }
    }
    __syncthreads();
    if (cnt == 0) return;
    for (int i = tid; i < T_DIM * D_DIM / 4; i += 128) {
        const int t = i >> 7, o = (i & 127) * 4;
        *(float4*)&xs[t * D_DIM + o] =
            *(const float4*)(x + ((size_t)t * M_DIM + m) * D_DIM + o);
    }
    __syncthreads();
    const int wid = tid >> 5, l = tid & 31;
    for (int i = wid; i < cnt; i += 4) {
        const int e = list[i], d = e & 511, mk = e >> 9;
        float sq[T_DIM], sk[T_DIM], sv[T_DIM];
        if (mk & 1) exact_spikes_warp(xs, Wq, d, l, sq); else prov_spikes(g_Yq, m, d, sq);
        if (mk & 2) exact_spikes_warp(xs, Wk, d, l, sk); else prov_spikes(g_Yk, m, d, sk);
        if (mk & 4) exact_spikes_warp(xs, Wv, d, l, sv); else prov_spikes(g_Yv, m, d, sv);
        if (l == 0) {
            float ctx = 0.f;
#pragma unroll
            for (int t = 0; t < T_DIM; t++) {
                ctx += sk[t] * sv[t];
                g_S[(size_t)t * MD + (size_t)m * D_DIM + d] = __float2half_rn(sq[t] * ctx);
            }
        }
    }
}

// ---------------- launch ----------------
extern "C" void kernel_launch(void* const* d_in, const int* in_sizes, int n_in,
                              void* d_out, int out_size) {
    (void)in_sizes; (void)n_in; (void)out_size;
    const float* x  = (const float*)d_in[0];
    const float* Wq = (const float*)d_in[1];
    const float* Wk = (const float*)d_in[2];
    const float* Wv = (const float*)d_in[3];
    const float* Wp = (const float*)d_in[4];
    const float* bp = (const float*)d_in[5];
    float* out = (float*)d_out;

    const int SMEM_QKV = 2 * 40960 + 128;
    const int SMEM_OUT = 3 * 32768 + 128;
    cudaFuncSetAttribute(qkv_gemm, cudaFuncAttributeMaxDynamicSharedMemorySize, SMEM_QKV);
    cudaFuncSetAttribute(out_gemm, cudaFuncAttributeMaxDynamicSharedMemorySize, SMEM_OUT);

    split_x<<<(int)(RD / 1024), 256>>>(x);
    prep_w<<<4096, 256>>>(Wq, Wk, Wv, Wp);

    qkv_gemm<<<dim3(8, R_DIM / 128), 256, SMEM_QKV>>>();

    lif_attn<<<(int)(MD / 4 / 256), 256>>>();

    repair<<<M_DIM, 128>>>(x, Wq, Wk, Wv);

    out_gemm<<<dim3(4, R_DIM / 128), 256, SMEM_OUT>>>(out, bp);
}

// round 13
// speedup vs baseline: 1.0539x; 1.0539x over previous
#include <cuda_runtime.h>
#include <cuda_fp16.h>
#include <cstdint>

#define T_DIM 4
#define M_DIM 16384
#define R_DIM 65536
#define D_DIM 512
#define MD ((size_t)M_DIM * D_DIM)
#define RD ((size_t)R_DIM * D_DIM)

// scratch (device globals; no allocs allowed)
__device__ __align__(16) __half  g_X0[RD];                 // fp16(x)
__device__ __align__(16) __half  g_Yq[RD];                 // projection outputs (fp16)
__device__ __align__(16) __half  g_Yk[RD];
__device__ __align__(16) __half  g_Yv[RD];
__device__ __align__(16) __half  g_S[RD];                  // spike-attention state (exact ints)
__device__ __align__(16) __half  g_Wh[4 * D_DIM * D_DIM];  // fp16 planes of Wq,Wk,Wv,Wp
__device__ __align__(4)  uint8_t g_flag[MD];               // per-(m,d) near-threshold mask

// ---------------- helpers ----------------
__device__ __forceinline__ uint32_t smem_u32(const void* p) {
    uint32_t a;
    asm("{ .reg .u64 t; cvta.to.shared.u64 t, %1; cvt.u32.u64 %0, t; }" : "=r"(a) : "l"(p));
    return a;
}
#define SW128(o) ((o) ^ (((o) >> 3) & 0x70))
#define CP_ASYNC16(sa, g) \
    asm volatile("cp.async.cg.shared.global [%0], [%1], 16;" :: "r"((uint32_t)(sa)), "l"(g))
#define CP_COMMIT() asm volatile("cp.async.commit_group;" ::: "memory")
#define CP_WAIT1()  asm volatile("cp.async.wait_group 1;" ::: "memory")
#define CP_WAIT0()  asm volatile("cp.async.wait_group 0;" ::: "memory")
#define LDMX4(r0, r1, r2, r3, a)                                            \
    asm volatile("ldmatrix.sync.aligned.m8n8.x4.shared.b16 {%0,%1,%2,%3}, [%4];" \
                 : "=r"(r0), "=r"(r1), "=r"(r2), "=r"(r3) : "r"(a))
#define MMA16816(c, a, b0, b1)                                              \
    asm volatile("mma.sync.aligned.m16n8k16.row.col.f32.f16.f16.f32 "       \
                 "{%0,%1,%2,%3},{%4,%5,%6,%7},{%8,%9},{%0,%1,%2,%3};"       \
                 : "+f"((c)[0]), "+f"((c)[1]), "+f"((c)[2]), "+f"((c)[3])   \
                 : "r"((a)[0]), "r"((a)[1]), "r"((a)[2]), "r"((a)[3]),      \
                   "r"(b0), "r"(b1))

// ---------------- fp32 -> fp16 pre-conversions ----------------
__global__ __launch_bounds__(256) void split_x(const float* __restrict__ x) {
    const size_t i = ((size_t)blockIdx.x * 256 + threadIdx.x) * 4;
    const float4 v = *(const float4*)(x + i);
    __half h[4] = {__float2half_rn(v.x), __float2half_rn(v.y),
                   __float2half_rn(v.z), __float2half_rn(v.w)};
    *(uint2*)&g_X0[i] = *(uint2*)h;
}

__global__ __launch_bounds__(256) void prep_w(const float* __restrict__ W0,
                                              const float* __restrict__ W1,
                                              const float* __restrict__ W2,
                                              const float* __restrict__ W3) {
    const int idx = blockIdx.x * 256 + threadIdx.x;   // 0 .. 4*262144-1
    const int mat = idx >> 18, rem = idx & 0x3FFFF;
    const float* W = (mat == 0) ? W0 : (mat == 1) ? W1 : (mat == 2) ? W2 : W3;
    g_Wh[(size_t)mat * 262144 + rem] = __float2half_rn(W[rem]);
}

// ---------------- HMMA GEMM body: 64x64 warp tiles, occ 2 -----------------
// C[m,n] = sum_k A[m,k] * B[n,k] (+bias). CTA 128x128 with 4 warps of 64x64:
// per k16 step 8 LDSM.x4 -> 32 MMA (R11 was 6:16). Crossbar traffic/SM -33%,
// 4x longer per-warp MMA chains, occ 2 kept (128 thr, ~200 regs, 96KB smem).
// 3-stage cp.async; last tile waits group 0 (R10 race fix). Per-element
// k-accumulation order identical to R11 -> bit-exact Y/spikes.
template <typename OT>
__device__ __forceinline__ void gemm64_body(const __half* __restrict__ A,
                                            const __half* __restrict__ B,
                                            OT* __restrict__ C,
                                            const float* __restrict__ bias,
                                            int bm, int bn, uint32_t sb) {
    const int tid = threadIdx.x, l = tid & 31, wid = tid >> 5;
    const int wm = (wid & 1) * 64, wn = (wid >> 1) * 64;

    float acc[4][8][4];
#pragma unroll
    for (int f = 0; f < 4; f++)
#pragma unroll
        for (int n8 = 0; n8 < 8; n8++)
#pragma unroll
            for (int i = 0; i < 4; i++) acc[f][n8][i] = 0.f;

    auto load_stage = [&](int kt, int st) {
        const int k0 = kt * 64;
        const uint32_t smA = sb + st * 32768, smB = smA + 16384;
#pragma unroll
        for (int j = 0; j < 8; j++) {          // 128 rows x 8 chunks, 128 threads
            const int row = j * 16 + (tid >> 3), ch = tid & 7;
            const uint32_t dst = SW128((uint32_t)(row * 128 + ch * 16));
            CP_ASYNC16(smA + dst, A + (size_t)(bm + row) * D_DIM + k0 + ch * 8);
            CP_ASYNC16(smB + dst, B + (size_t)(bn + row) * D_DIM + k0 + ch * 8);
        }
        CP_COMMIT();
    };

    load_stage(0, 0);
    load_stage(1, 1);
    for (int kt = 0; kt < 8; kt++) {
        if (kt < 7) CP_WAIT1(); else CP_WAIT0();   // tile kt landed
        __syncthreads();
        if (kt + 2 < 8) load_stage(kt + 2, (kt + 2) % 3);
        const uint32_t smA = sb + (kt % 3) * 32768, smB = smA + 16384;
#pragma unroll
        for (int s = 0; s < 4; s++) {
            uint32_t afr[4][4];
#pragma unroll
            for (int f = 0; f < 4; f++) {      // A: m64 x k16
                const int row = wm + f * 16 + (l & 15);
                const int ch = 2 * s + (l >> 4);
                LDMX4(afr[f][0], afr[f][1], afr[f][2], afr[f][3],
                      smA + SW128((uint32_t)(row * 128 + ch * 16)));
            }
            uint32_t bfr[4][4];
#pragma unroll
            for (int h = 0; h < 4; h++) {      // B: n64 x k16
                const int row = wn + h * 16 + (l & 7) + ((l >> 4) << 3);
                const int ch = 2 * s + ((l >> 3) & 1);
                LDMX4(bfr[h][0], bfr[h][1], bfr[h][2], bfr[h][3],
                      smB + SW128((uint32_t)(row * 128 + ch * 16)));
            }
#pragma unroll
            for (int f = 0; f < 4; f++)
#pragma unroll
                for (int h = 0; h < 4; h++) {
                    MMA16816(acc[f][2 * h],     afr[f], bfr[h][0], bfr[h][1]);
                    MMA16816(acc[f][2 * h + 1], afr[f], bfr[h][2], bfr[h][3]);
                }
        }
    }

    const int er = l >> 2, ec = (l & 3) * 2;
#pragma unroll
    for (int f = 0; f < 4; f++) {
        const int m = bm + wm + f * 16 + er;
#pragma unroll
        for (int n8 = 0; n8 < 8; n8++) {
            const int n = bn + wn + n8 * 8 + ec;
            float b0v = 0.f, b1v = 0.f;
            if (bias) { b0v = bias[n]; b1v = bias[n + 1]; }
            if constexpr (sizeof(OT) == 2) {
                *(__half2*)&C[(size_t)m * D_DIM + n] =
                    __floats2half2_rn(acc[f][n8][0] + b0v, acc[f][n8][1] + b1v);
                *(__half2*)&C[(size_t)(m + 8) * D_DIM + n] =
                    __floats2half2_rn(acc[f][n8][2] + b0v, acc[f][n8][3] + b1v);
            } else {
                *(float2*)&C[(size_t)m * D_DIM + n] =
                    make_float2(acc[f][n8][0] + b0v, acc[f][n8][1] + b1v);
                *(float2*)&C[(size_t)(m + 8) * D_DIM + n] =
                    make_float2(acc[f][n8][2] + b0v, acc[f][n8][3] + b1v);
            }
        }
    }
}

// Per-matrix projection launches (R11 structure): grid (12, 512), mat = bx>>2.
__global__ __launch_bounds__(128, 2) void proj_gemm() {
    extern __shared__ __align__(128) char sm_raw[];
    const uint32_t sb = (smem_u32(sm_raw) + 127) & ~127u;
    const int mat = blockIdx.x >> 2;
    const int bn = (blockIdx.x & 3) * 128;
    const int bm = blockIdx.y * 128;
    __half* C = (mat == 0) ? g_Yq : (mat == 1) ? g_Yk : g_Yv;
    gemm64_body<__half>(g_X0, g_Wh + (size_t)mat * 262144, C, nullptr, bm, bn, sb);
}

__global__ __launch_bounds__(128, 2) void out_gemm(float* __restrict__ out,
                                                   const float* __restrict__ bias) {
    extern __shared__ __align__(128) char sm_raw[];
    const uint32_t sb = (smem_u32(sm_raw) + 127) & ~127u;
    gemm64_body<float>(g_S, g_Wh + (size_t)3 * 262144, out,
                       bias, blockIdx.y * 128, blockIdx.x * 128, sb);
}

// ---------------- LIF provisional pass (EPS=5e-3 validated zero-flip margin) ------------
#define LIF_EPS 5e-3f

__global__ __launch_bounds__(256) void lif_attn() {
    const size_t base = ((size_t)blockIdx.x * 256 + threadIdx.x) * 4;

    __half q[T_DIM][4], k[T_DIM][4], v[T_DIM][4], s[T_DIM][4];
#pragma unroll
    for (int t = 0; t < T_DIM; t++) {
        *(uint2*)q[t] = *(const uint2*)&g_Yq[(size_t)t * MD + base];
        *(uint2*)k[t] = *(const uint2*)&g_Yk[(size_t)t * MD + base];
        *(uint2*)v[t] = *(const uint2*)&g_Yv[(size_t)t * MD + base];
    }
    uint32_t flags = 0;
#pragma unroll
    for (int c = 0; c < 4; c++) {
        float sq[T_DIM], sk[T_DIM], sv[T_DIM];
        uint32_t mk = 0;
        float mq = 0.f, mkm = 0.f, mv = 0.f;
#pragma unroll
        for (int t = 0; t < T_DIM; t++) {
            mq = fmaf(0.9f, mq, __half2float(q[t][c]));
            if (fabsf(mq - 1.0f) < LIF_EPS) mk |= 1u;
            sq[t] = (mq >= 1.0f) ? 1.0f : 0.0f; mq -= sq[t];
            mkm = fmaf(0.9f, mkm, __half2float(k[t][c]));
            if (fabsf(mkm - 1.0f) < LIF_EPS) mk |= 2u;
            sk[t] = (mkm >= 1.0f) ? 1.0f : 0.0f; mkm -= sk[t];
            mv = fmaf(0.9f, mv, __half2float(v[t][c]));
            if (fabsf(mv - 1.0f) < LIF_EPS) mk |= 4u;
            sv[t] = (mv >= 1.0f) ? 1.0f : 0.0f; mv -= sv[t];
        }
        flags |= mk << (8 * c);
        float ctx = 0.f;
#pragma unroll
        for (int t = 0; t < T_DIM; t++) {
            ctx += sk[t] * sv[t];
            s[t][c] = __float2half_rn(sq[t] * ctx);   // exact: small integers
        }
    }
    *(uint32_t*)&g_flag[base] = flags;   // mostly 0
#pragma unroll
    for (int t = 0; t < T_DIM; t++)
        *(uint2*)&g_S[(size_t)t * MD + base] = *(uint2*)s[t];
}

// ---------------- exact repair: one CTA per m, x rows staged in smem ------------
__device__ __forceinline__ void exact_spikes_warp(const float* __restrict__ xs,
                                                  const float* __restrict__ W,
                                                  int d, int l, float* sp) {
    const float* w = W + (size_t)d * D_DIM;
    float wv[16];
#pragma unroll
    for (int j = 0; j < 16; j++) wv[j] = w[l * 16 + j];
    float mem = 0.f;
    for (int t = 0; t < T_DIM; t++) {
        const float* xr = xs + t * D_DIM;
        float p = 0.f;
#pragma unroll
        for (int j = 0; j < 16; j++) p = fmaf(xr[l * 16 + j], wv[j], p);
#pragma unroll
        for (int off = 16; off > 0; off >>= 1) p += __shfl_xor_sync(0xffffffffu, p, off);
        mem = fmaf(0.9f, mem, p);
        sp[t] = (mem >= 1.0f) ? 1.0f : 0.0f;
        mem -= sp[t];
    }
}

__device__ __forceinline__ void prov_spikes(const __half* __restrict__ Y,
                                            int m, int d, float* sp) {
    float mem = 0.f;
    for (int t = 0; t < T_DIM; t++) {
        mem = fmaf(0.9f, mem, __half2float(Y[(size_t)t * MD + (size_t)m * D_DIM + d]));
        sp[t] = (mem >= 1.0f) ? 1.0f : 0.0f;
        mem -= sp[t];
    }
}

__global__ __launch_bounds__(128) void repair(const float* __restrict__ x,
                                              const float* __restrict__ Wq,
                                              const float* __restrict__ Wk,
                                              const float* __restrict__ Wv) {
    const int m = blockIdx.x;
    __shared__ float xs[T_DIM * D_DIM];   // 8KB: the 4 x rows of this m
    __shared__ uint16_t list[512];
    __shared__ int cnt;
    const int tid = threadIdx.x;
    if (tid == 0) cnt = 0;
    __syncthreads();
    for (int d = tid; d < D_DIM; d += 128) {
        const uint32_t mk = g_flag[(size_t)m * D_DIM + d];
        if (mk) { int p = atomicAdd(&cnt, 1); list[p] = (uint16_t)(d | (mk << 9)); }
    }
    __syncthreads();
    if (cnt == 0) return;
    for (int i = tid; i < T_DIM * D_DIM / 4; i += 128) {
        const int t = i >> 7, o = (i & 127) * 4;
        *(float4*)&xs[t * D_DIM + o] =
            *(const float4*)(x + ((size_t)t * M_DIM + m) * D_DIM + o);
    }
    __syncthreads();
    const int wid = tid >> 5, l = tid & 31;
    for (int i = wid; i < cnt; i += 4) {
        const int e = list[i], d = e & 511, mk = e >> 9;
        float sq[T_DIM], sk[T_DIM], sv[T_DIM];
        if (mk & 1) exact_spikes_warp(xs, Wq, d, l, sq); else prov_spikes(g_Yq, m, d, sq);
        if (mk & 2) exact_spikes_warp(xs, Wk, d, l, sk); else prov_spikes(g_Yk, m, d, sk);
        if (mk & 4) exact_spikes_warp(xs, Wv, d, l, sv); else prov_spikes(g_Yv, m, d, sv);
        if (l == 0) {
            float ctx = 0.f;
#pragma unroll
            for (int t = 0; t < T_DIM; t++) {
                ctx += sk[t] * sv[t];
                g_S[(size_t)t * MD + (size_t)m * D_DIM + d] = __float2half_rn(sq[t] * ctx);
            }
        }
    }
}

// ---------------- launch ----------------
extern "C" void kernel_launch(void* const* d_in, const int* in_sizes, int n_in,
                              void* d_out, int out_size) {
    (void)in_sizes; (void)n_in; (void)out_size;
    const float* x  = (const float*)d_in[0];
    const float* Wq = (const float*)d_in[1];
    const float* Wk = (const float*)d_in[2];
    const float* Wv = (const float*)d_in[3];
    const float* Wp = (const float*)d_in[4];
    const float* bp = (const float*)d_in[5];
    float* out = (float*)d_out;

    const int SMEM = 3 * 32768 + 128;
    cudaFuncSetAttribute(proj_gemm, cudaFuncAttributeMaxDynamicSharedMemorySize, SMEM);
    cudaFuncSetAttribute(out_gemm,  cudaFuncAttributeMaxDynamicSharedMemorySize, SMEM);

    split_x<<<(int)(RD / 1024), 256>>>(x);
    prep_w<<<4096, 256>>>(Wq, Wk, Wv, Wp);

    proj_gemm<<<dim3(12, R_DIM / 128), 128, SMEM>>>();

    lif_attn<<<(int)(MD / 4 / 256), 256>>>();

    repair<<<M_DIM, 128>>>(x, Wq, Wk, Wv);

    out_gemm<<<dim3(4, R_DIM / 128), 128, SMEM>>>(out, bp);
}

// round 14
// speedup vs baseline: 1.0865x; 1.0309x over previous
#include <cuda_runtime.h>
#include <cuda_fp16.h>
#include <cstdint>

#define T_DIM 4
#define M_DIM 16384
#define R_DIM 65536
#define D_DIM 512
#define MD ((size_t)M_DIM * D_DIM)
#define RD ((size_t)R_DIM * D_DIM)

// scratch (device globals; no allocs allowed)
__device__ __align__(16) __half  g_X0[RD];                 // fp16(x)
__device__ __align__(16) __half  g_S[RD];                  // spike-attention state (exact ints)
__device__ __align__(16) __half  g_Wh[4 * D_DIM * D_DIM];  // fp16 planes of Wq,Wk,Wv,Wp
// per (mat, m, d): spike nibble (bits 0..3 = t) | flag (bit 7 = near-threshold)
__device__ __align__(4)  uint8_t g_spk[3 * MD];

// ---------------- helpers ----------------
__device__ __forceinline__ uint32_t smem_u32(const void* p) {
    uint32_t a;
    asm("{ .reg .u64 t; cvta.to.shared.u64 t, %1; cvt.u32.u64 %0, t; }" : "=r"(a) : "l"(p));
    return a;
}
#define SW128(o) ((o) ^ (((o) >> 3) & 0x70))
#define CP_ASYNC16(sa, g) \
    asm volatile("cp.async.cg.shared.global [%0], [%1], 16;" :: "r"((uint32_t)(sa)), "l"(g))
#define CP_COMMIT() asm volatile("cp.async.commit_group;" ::: "memory")
#define CP_WAIT1()  asm volatile("cp.async.wait_group 1;" ::: "memory")
#define CP_WAIT0()  asm volatile("cp.async.wait_group 0;" ::: "memory")
#define LDMX4(r0, r1, r2, r3, a)                                            \
    asm volatile("ldmatrix.sync.aligned.m8n8.x4.shared.b16 {%0,%1,%2,%3}, [%4];" \
                 : "=r"(r0), "=r"(r1), "=r"(r2), "=r"(r3) : "r"(a))
#define MMA16816(c, a, b0, b1)                                              \
    asm volatile("mma.sync.aligned.m16n8k16.row.col.f32.f16.f16.f32 "       \
                 "{%0,%1,%2,%3},{%4,%5,%6,%7},{%8,%9},{%0,%1,%2,%3};"       \
                 : "+f"((c)[0]), "+f"((c)[1]), "+f"((c)[2]), "+f"((c)[3])   \
                 : "r"((a)[0]), "r"((a)[1]), "r"((a)[2]), "r"((a)[3]),      \
                   "r"(b0), "r"(b1))

#define LIF_EPS 5e-3f   // validated zero-flip margin (R9/R11/R13)

// ---------------- fp32 -> fp16 pre-conversions ----------------
__global__ __launch_bounds__(256) void split_x(const float* __restrict__ x) {
    const size_t i = ((size_t)blockIdx.x * 256 + threadIdx.x) * 4;
    const float4 v = *(const float4*)(x + i);
    __half h[4] = {__float2half_rn(v.x), __float2half_rn(v.y),
                   __float2half_rn(v.z), __float2half_rn(v.w)};
    *(uint2*)&g_X0[i] = *(uint2*)h;
}

__global__ __launch_bounds__(256) void prep_w(const float* __restrict__ W0,
                                              const float* __restrict__ W1,
                                              const float* __restrict__ W2,
                                              const float* __restrict__ W3) {
    const int idx = blockIdx.x * 256 + threadIdx.x;
    const int mat = idx >> 18, rem = idx & 0x3FFFF;
    const float* W = (mat == 0) ? W0 : (mat == 1) ? W1 : (mat == 2) ? W2 : W3;
    g_Wh[(size_t)mat * 262144 + rem] = __float2half_rn(W[rem]);
}

// ---------------- fused projection + LIF (one matrix per launch) ----------------
// CTA tile = 128 gathered A rows (4 time-steps x 32 m-rows; row j -> global row
// (j>>5)*M + bm + (j&31)) x 128 n. Mainloop = R13's 64x64-warp HMMA (bit-identical
// k-order). Epilogue: acc -> fp16 in smem (same quantization as R13's Y store ->
// bit-identical membranes), then per-(m,d) LIF chains over the 4 staged t-values;
// emits spike nibble + near-threshold flag byte. Y never touches DRAM.
template <int MAT>
__global__ __launch_bounds__(128, 2) void proj_fused() {
    extern __shared__ __align__(128) char sm_raw[];
    const uint32_t raw = smem_u32(sm_raw);
    const uint32_t sb = (raw + 127) & ~127u;
    char* sbp = sm_raw + (sb - raw);

    const int tid = threadIdx.x, l = tid & 31, wid = tid >> 5;
    const int wm = (wid & 1) * 64, wn = (wid >> 1) * 64;
    const int bm = blockIdx.y * 32;     // 32 m-rows per CTA (x 4 t)
    const int bn = blockIdx.x * 128;

    float acc[4][8][4];
#pragma unroll
    for (int f = 0; f < 4; f++)
#pragma unroll
        for (int n8 = 0; n8 < 8; n8++)
#pragma unroll
            for (int i = 0; i < 4; i++) acc[f][n8][i] = 0.f;

    auto load_stage = [&](int kt, int st) {
        const int k0 = kt * 64;
        const uint32_t smA = sb + st * 32768, smB = smA + 16384;
#pragma unroll
        for (int j = 0; j < 8; j++) {
            const int row = j * 16 + (tid >> 3), ch = tid & 7;
            const uint32_t dst = SW128((uint32_t)(row * 128 + ch * 16));
            // gathered A row: time-step row>>5, m-row bm + (row&31)
            CP_ASYNC16(smA + dst,
                       g_X0 + ((size_t)(row >> 5) * M_DIM + bm + (row & 31)) * D_DIM + k0 + ch * 8);
            CP_ASYNC16(smB + dst,
                       g_Wh + (size_t)MAT * 262144 + (size_t)(bn + row) * D_DIM + k0 + ch * 8);
        }
        CP_COMMIT();
    };

    load_stage(0, 0);
    load_stage(1, 1);
    for (int kt = 0; kt < 8; kt++) {
        if (kt < 7) CP_WAIT1(); else CP_WAIT0();   // last tile must drain (R10 race fix)
        __syncthreads();
        if (kt + 2 < 8) load_stage(kt + 2, (kt + 2) % 3);
        const uint32_t smA = sb + (kt % 3) * 32768, smB = smA + 16384;
#pragma unroll
        for (int s = 0; s < 4; s++) {
            uint32_t afr[4][4];
#pragma unroll
            for (int f = 0; f < 4; f++) {
                const int row = wm + f * 16 + (l & 15);
                const int ch = 2 * s + (l >> 4);
                LDMX4(afr[f][0], afr[f][1], afr[f][2], afr[f][3],
                      smA + SW128((uint32_t)(row * 128 + ch * 16)));
            }
            uint32_t bfr[4][4];
#pragma unroll
            for (int h = 0; h < 4; h++) {
                const int row = wn + h * 16 + (l & 7) + ((l >> 4) << 3);
                const int ch = 2 * s + ((l >> 3) & 1);
                LDMX4(bfr[h][0], bfr[h][1], bfr[h][2], bfr[h][3],
                      smB + SW128((uint32_t)(row * 128 + ch * 16)));
            }
#pragma unroll
            for (int f = 0; f < 4; f++)
#pragma unroll
                for (int h = 0; h < 4; h++) {
                    MMA16816(acc[f][2 * h],     afr[f], bfr[h][0], bfr[h][1]);
                    MMA16816(acc[f][2 * h + 1], afr[f], bfr[h][2], bfr[h][3]);
                }
        }
    }

    // ---- epilogue: stage Y (fp16, R13-identical quantization) in smem ----
    __syncthreads();                       // all warps done with pipeline smem
    constexpr int PAD = 132;               // halfs per row (bank-spread)
    __half* Ysm = (__half*)sbp;            // 128 x 132 fp16 = 33.8KB, aliases stages
    const int er = l >> 2, ec = (l & 3) * 2;
#pragma unroll
    for (int f = 0; f < 4; f++) {
        const int m = wm + f * 16 + er;
#pragma unroll
        for (int n8 = 0; n8 < 8; n8++) {
            const int n = wn + n8 * 8 + ec;
            *(__half2*)&Ysm[m * PAD + n] = __floats2half2_rn(acc[f][n8][0], acc[f][n8][1]);
            *(__half2*)&Ysm[(m + 8) * PAD + n] = __floats2half2_rn(acc[f][n8][2], acc[f][n8][3]);
        }
    }
    __syncthreads();

    // ---- LIF chains: 4096 (m,d) chains, 32 per thread ----
    uint8_t* spk = g_spk + (size_t)MAT * MD;
#pragma unroll 4
    for (int i = 0; i < 32; i++) {
        const int c = i * 128 + tid;
        const int ml = c >> 7, n = c & 127;
        float mem = 0.f;
        uint32_t nib = 0, flg = 0;
#pragma unroll
        for (int t = 0; t < T_DIM; t++) {
            const float y = __half2float(Ysm[(t * 32 + ml) * PAD + n]);
            mem = fmaf(0.9f, mem, y);              // bit-identical to prior lif_attn
            if (fabsf(mem - 1.0f) < LIF_EPS) flg = 0x80u;
            const float s = (mem >= 1.0f) ? 1.0f : 0.0f;
            nib |= ((mem >= 1.0f) ? 1u : 0u) << t;
            mem -= s;
        }
        spk[(size_t)(bm + ml) * D_DIM + bn + n] = (uint8_t)(nib | flg);
    }
}

// ---------------- combine: S = q_spike * cumsum_t(k_spike * v_spike) ----------------
__global__ __launch_bounds__(256) void combine() {
    const size_t base = ((size_t)blockIdx.x * 256 + threadIdx.x) * 4;
    uchar4 qb = *(const uchar4*)&g_spk[0 * MD + base];
    uchar4 kb = *(const uchar4*)&g_spk[1 * MD + base];
    uchar4 vb = *(const uchar4*)&g_spk[2 * MD + base];
    const uint8_t* qa = &qb.x; const uint8_t* ka = &kb.x; const uint8_t* va = &vb.x;
    __half s[T_DIM][4];
#pragma unroll
    for (int c = 0; c < 4; c++) {
        const uint32_t qn = qa[c], kn = ka[c], vn = va[c];
        int ctx = 0;
#pragma unroll
        for (int t = 0; t < T_DIM; t++) {
            ctx += (int)((kn >> t) & 1u & (vn >> t));
            s[t][c] = __float2half_rn((float)((int)((qn >> t) & 1u) * ctx));
        }
    }
#pragma unroll
    for (int t = 0; t < T_DIM; t++)
        *(uint2*)&g_S[(size_t)t * MD + base] = *(uint2*)s[t];
}

// ---------------- exact repair: one CTA per m, x rows staged in smem ------------
__device__ __forceinline__ void exact_spikes_warp(const float* __restrict__ xs,
                                                  const float* __restrict__ W,
                                                  int d, int l, float* sp) {
    const float* w = W + (size_t)d * D_DIM;
    float wv[16];
#pragma unroll
    for (int j = 0; j < 16; j++) wv[j] = w[l * 16 + j];
    float mem = 0.f;
    for (int t = 0; t < T_DIM; t++) {
        const float* xr = xs + t * D_DIM;
        float p = 0.f;
#pragma unroll
        for (int j = 0; j < 16; j++) p = fmaf(xr[l * 16 + j], wv[j], p);
#pragma unroll
        for (int off = 16; off > 0; off >>= 1) p += __shfl_xor_sync(0xffffffffu, p, off);
        mem = fmaf(0.9f, mem, p);
        sp[t] = (mem >= 1.0f) ? 1.0f : 0.0f;
        mem -= sp[t];
    }
}

__global__ __launch_bounds__(128) void repair(const float* __restrict__ x,
                                              const float* __restrict__ Wq,
                                              const float* __restrict__ Wk,
                                              const float* __restrict__ Wv) {
    const int m = blockIdx.x;
    __shared__ float xs[T_DIM * D_DIM];   // 8KB: the 4 x rows of this m
    __shared__ uint16_t list[512];
    __shared__ int cnt;
    const int tid = threadIdx.x;
    if (tid == 0) cnt = 0;
    __syncthreads();
    for (int d = tid; d < D_DIM; d += 128) {
        const size_t idx = (size_t)m * D_DIM + d;
        const uint32_t mk = ((g_spk[idx] >> 7) & 1u) | ((g_spk[MD + idx] >> 7) & 1u) << 1 |
                            ((g_spk[2 * MD + idx] >> 7) & 1u) << 2;
        if (mk) { int p = atomicAdd(&cnt, 1); list[p] = (uint16_t)(d | (mk << 9)); }
    }
    __syncthreads();
    if (cnt == 0) return;
    for (int i = tid; i < T_DIM * D_DIM / 4; i += 128) {
        const int t = i >> 7, o = (i & 127) * 4;
        *(float4*)&xs[t * D_DIM + o] =
            *(const float4*)(x + ((size_t)t * M_DIM + m) * D_DIM + o);
    }
    __syncthreads();
    const int wid = tid >> 5, l = tid & 31;
    for (int i = wid; i < cnt; i += 4) {
        const int e = list[i], d = e & 511, mk = e >> 9;
        const size_t idx = (size_t)m * D_DIM + d;
        float sq[T_DIM], sk[T_DIM], sv[T_DIM];
#pragma unroll
        for (int t = 0; t < T_DIM; t++) {     // provisional spikes from nibbles
            sq[t] = (float)((g_spk[idx] >> t) & 1u);
            sk[t] = (float)((g_spk[MD + idx] >> t) & 1u);
            sv[t] = (float)((g_spk[2 * MD + idx] >> t) & 1u);
        }
        if (mk & 1) exact_spikes_warp(xs, Wq, d, l, sq);
        if (mk & 2) exact_spikes_warp(xs, Wk, d, l, sk);
        if (mk & 4) exact_spikes_warp(xs, Wv, d, l, sv);
        if (l == 0) {
            float ctx = 0.f;
#pragma unroll
            for (int t = 0; t < T_DIM; t++) {
                ctx += sk[t] * sv[t];
                g_S[(size_t)t * MD + idx] = __float2half_rn(sq[t] * ctx);
            }
        }
    }
}

// ---------------- output GEMM (R13-validated 64x64-warp body) ----------------
__global__ __launch_bounds__(128, 2) void out_gemm(float* __restrict__ C,
                                                   const float* __restrict__ bias) {
    extern __shared__ __align__(128) char sm_raw[];
    const uint32_t sb = (smem_u32(sm_raw) + 127) & ~127u;
    const __half* A = g_S;
    const __half* B = g_Wh + (size_t)3 * 262144;
    const int bm = blockIdx.y * 128, bn = blockIdx.x * 128;
    const int tid = threadIdx.x, l = tid & 31, wid = tid >> 5;
    const int wm = (wid & 1) * 64, wn = (wid >> 1) * 64;

    float acc[4][8][4];
#pragma unroll
    for (int f = 0; f < 4; f++)
#pragma unroll
        for (int n8 = 0; n8 < 8; n8++)
#pragma unroll
            for (int i = 0; i < 4; i++) acc[f][n8][i] = 0.f;

    auto load_stage = [&](int kt, int st) {
        const int k0 = kt * 64;
        const uint32_t smA = sb + st * 32768, smB = smA + 16384;
#pragma unroll
        for (int j = 0; j < 8; j++) {
            const int row = j * 16 + (tid >> 3), ch = tid & 7;
            const uint32_t dst = SW128((uint32_t)(row * 128 + ch * 16));
            CP_ASYNC16(smA + dst, A + (size_t)(bm + row) * D_DIM + k0 + ch * 8);
            CP_ASYNC16(smB + dst, B + (size_t)(bn + row) * D_DIM + k0 + ch * 8);
        }
        CP_COMMIT();
    };

    load_stage(0, 0);
    load_stage(1, 1);
    for (int kt = 0; kt < 8; kt++) {
        if (kt < 7) CP_WAIT1(); else CP_WAIT0();
        __syncthreads();
        if (kt + 2 < 8) load_stage(kt + 2, (kt + 2) % 3);
        const uint32_t smA = sb + (kt % 3) * 32768, smB = smA + 16384;
#pragma unroll
        for (int s = 0; s < 4; s++) {
            uint32_t afr[4][4];
#pragma unroll
            for (int f = 0; f < 4; f++) {
                const int row = wm + f * 16 + (l & 15);
                const int ch = 2 * s + (l >> 4);
                LDMX4(afr[f][0], afr[f][1], afr[f][2], afr[f][3],
                      smA + SW128((uint32_t)(row * 128 + ch * 16)));
            }
            uint32_t bfr[4][4];
#pragma unroll
            for (int h = 0; h < 4; h++) {
                const int row = wn + h * 16 + (l & 7) + ((l >> 4) << 3);
                const int ch = 2 * s + ((l >> 3) & 1);
                LDMX4(bfr[h][0], bfr[h][1], bfr[h][2], bfr[h][3],
                      smB + SW128((uint32_t)(row * 128 + ch * 16)));
            }
#pragma unroll
            for (int f = 0; f < 4; f++)
#pragma unroll
                for (int h = 0; h < 4; h++) {
                    MMA16816(acc[f][2 * h],     afr[f], bfr[h][0], bfr[h][1]);
                    MMA16816(acc[f][2 * h + 1], afr[f], bfr[h][2], bfr[h][3]);
                }
        }
    }

    const int er = l >> 2, ec = (l & 3) * 2;
#pragma unroll
    for (int f = 0; f < 4; f++) {
        const int m = bm + wm + f * 16 + er;
#pragma unroll
        for (int n8 = 0; n8 < 8; n8++) {
            const int n = bn + wn + n8 * 8 + ec;
            const float b0v = bias[n], b1v = bias[n + 1];
            *(float2*)&C[(size_t)m * D_DIM + n] =
                make_float2(acc[f][n8][0] + b0v, acc[f][n8][1] + b1v);
            *(float2*)&C[(size_t)(m + 8) * D_DIM + n] =
                make_float2(acc[f][n8][2] + b0v, acc[f][n8][3] + b1v);
        }
    }
}

// ---------------- launch ----------------
extern "C" void kernel_launch(void* const* d_in, const int* in_sizes, int n_in,
                              void* d_out, int out_size) {
    (void)in_sizes; (void)n_in; (void)out_size;
    const float* x  = (const float*)d_in[0];
    const float* Wq = (const float*)d_in[1];
    const float* Wk = (const float*)d_in[2];
    const float* Wv = (const float*)d_in[3];
    const float* Wp = (const float*)d_in[4];
    const float* bp = (const float*)d_in[5];
    float* out = (float*)d_out;

    const int SMEM = 3 * 32768 + 128;
    cudaFuncSetAttribute(proj_fused<0>, cudaFuncAttributeMaxDynamicSharedMemorySize, SMEM);
    cudaFuncSetAttribute(proj_fused<1>, cudaFuncAttributeMaxDynamicSharedMemorySize, SMEM);
    cudaFuncSetAttribute(proj_fused<2>, cudaFuncAttributeMaxDynamicSharedMemorySize, SMEM);
    cudaFuncSetAttribute(out_gemm, cudaFuncAttributeMaxDynamicSharedMemorySize, SMEM);

    split_x<<<(int)(RD / 1024), 256>>>(x);
    prep_w<<<4096, 256>>>(Wq, Wk, Wv, Wp);

    dim3 pgrid(D_DIM / 128, M_DIM / 32);   // (4, 512)
    proj_fused<0><<<pgrid, 128, SMEM>>>();
    proj_fused<1><<<pgrid, 128, SMEM>>>();
    proj_fused<2><<<pgrid, 128, SMEM>>>();

    combine<<<(int)(MD / 4 / 256), 256>>>();

    repair<<<M_DIM, 128>>>(x, Wq, Wk, Wv);

    out_gemm<<<dim3(4, R_DIM / 128), 128, SMEM>>>(out, bp);
}